// round 1
// baseline (speedup 1.0000x reference)
#include <cuda_runtime.h>
#include <cuda_bf16.h>
#include <math_constants.h>

// Problem constants
#define B   4
#define S   2048
#define NX  1024
#define H   16
#define D   64          // head dim
#define M_TOT (B * S)   // 8192 rows

// Scratch (no cudaMalloc allowed): qkv buffer + context buffer
__device__ float g_qkv[(size_t)M_TOT * 3 * NX];   // (B*S, 3072)
__device__ float g_ctx[(size_t)M_TOT * NX];       // (B*S, 1024) merged heads

// ----------------------------------------------------------------------------
// SGEMM with bias: C[M,N] = A[M,K] @ B[K,N] + bias[N]
// Block tile 128x128, K-tile 8, 256 threads, 8x8 per thread.
// Requires M%128==0, N%128==0, K%8==0 (true for all our shapes).
// ----------------------------------------------------------------------------
#define BM 128
#define BN 128
#define BK 8

__global__ __launch_bounds__(256)
void sgemm_bias(const float* __restrict__ A, const float* __restrict__ Bm,
                const float* __restrict__ bias, float* __restrict__ C,
                int M, int N, int K)
{
    __shared__ float As[BK][BM];      // A transposed tile
    __shared__ float Bs[BK][BN];

    const int tid = threadIdx.x;
    const int block_row = blockIdx.y * BM;
    const int block_col = blockIdx.x * BN;

    // A tile load indices: 128 rows x 8 k = 256 float4
    const int a_row = tid >> 1;            // 0..127
    const int a_col = (tid & 1) * 4;       // 0 or 4
    // B tile load indices: 8 rows x 128 cols = 256 float4
    const int b_row = tid >> 5;            // 0..7
    const int b_col = (tid & 31) * 4;      // 0..124

    const int ty = tid >> 4;   // 0..15  (row group)
    const int tx = tid & 15;   // 0..15  (col group)

    float acc[8][8];
#pragma unroll
    for (int i = 0; i < 8; i++)
#pragma unroll
        for (int j = 0; j < 8; j++) acc[i][j] = 0.f;

    const float* a_ptr = A + (size_t)(block_row + a_row) * K + a_col;
    const float* b_ptr = Bm + (size_t)b_row * N + block_col + b_col;

    for (int k0 = 0; k0 < K; k0 += BK) {
        float4 av = *(const float4*)(a_ptr + k0);
        As[a_col + 0][a_row] = av.x;
        As[a_col + 1][a_row] = av.y;
        As[a_col + 2][a_row] = av.z;
        As[a_col + 3][a_row] = av.w;
        float4 bv = *(const float4*)(b_ptr + (size_t)k0 * N);
        *(float4*)&Bs[b_row][b_col] = bv;
        __syncthreads();

#pragma unroll
        for (int k = 0; k < BK; k++) {
            float a[8], b[8];
            *(float4*)(a)     = *(const float4*)&As[k][ty * 8];
            *(float4*)(a + 4) = *(const float4*)&As[k][ty * 8 + 4];
            *(float4*)(b)     = *(const float4*)&Bs[k][tx * 8];
            *(float4*)(b + 4) = *(const float4*)&Bs[k][tx * 8 + 4];
#pragma unroll
            for (int i = 0; i < 8; i++)
#pragma unroll
                for (int j = 0; j < 8; j++)
                    acc[i][j] = fmaf(a[i], b[j], acc[i][j]);
        }
        __syncthreads();
    }

    // Epilogue: add bias, store
#pragma unroll
    for (int i = 0; i < 8; i++) {
        const size_t row = block_row + ty * 8 + i;
#pragma unroll
        for (int j = 0; j < 8; j += 4) {
            const int col = block_col + tx * 8 + j;
            float4 bv = *(const float4*)(bias + col);
            float4 cv;
            cv.x = acc[i][j + 0] + bv.x;
            cv.y = acc[i][j + 1] + bv.y;
            cv.z = acc[i][j + 2] + bv.z;
            cv.w = acc[i][j + 3] + bv.w;
            *(float4*)(C + row * N + col) = cv;
        }
    }
}

// ----------------------------------------------------------------------------
// Flash-attention (fp32 SIMT, online softmax).
// Grid: (S/64, B*H). Block: 256 threads (16x16).
// Each block: 64 query rows x D=64, loops over 32 key tiles of 64.
// Thread (ty,tx): scores s[4q][4k]; output o[4q][4d].
// smem (dynamic): QsT[64d][68q] KsT[64d][68k] Vs[64k][68d] PsT[64k][68q] mask[64]
// ----------------------------------------------------------------------------
#define PAD 68
#define TQ  64
#define TK  64

__global__ __launch_bounds__(256)
void flash_attn(const float* __restrict__ qkv, const float* __restrict__ mask,
                float* __restrict__ ctx)
{
    extern __shared__ float sm[];
    float* QsT = sm;                    // [64][PAD] (d-major)
    float* KsT = QsT + 64 * PAD;        // [64][PAD] (d-major)
    float* Vs  = KsT + 64 * PAD;        // [64][PAD] (k-major)
    float* PsT = Vs  + 64 * PAD;        // [64][PAD] (k-major, prob transposed)
    float* mk  = PsT + 64 * PAD;        // [64]

    const int bh = blockIdx.y;
    const int b  = bh >> 4;             // /16
    const int h  = bh & 15;
    const int q0 = blockIdx.x * TQ;

    const int tid = threadIdx.x;
    const int tx = tid & 15;            // key / d-col group
    const int ty = tid >> 4;            // query row group

    const size_t base = (size_t)b * S * (3 * NX);
    const float* qptr = qkv + base + (size_t)h * D;             // Q
    const float* kptr = qkv + base + NX + (size_t)h * D;        // K
    const float* vptr = qkv + base + 2 * NX + (size_t)h * D;    // V

    // Load Q tile transposed: QsT[d][r]
    for (int idx = tid; idx < TQ * D; idx += 256) {
        const int r = idx >> 6;         // /64
        const int d = idx & 63;
        QsT[d * PAD + r] = qptr[(size_t)(q0 + r) * (3 * NX) + d];
    }

    float m_i[4], l_i[4];
    float o[4][4];
#pragma unroll
    for (int i = 0; i < 4; i++) {
        m_i[i] = -CUDART_INF_F;
        l_i[i] = 0.f;
#pragma unroll
        for (int j = 0; j < 4; j++) o[i][j] = 0.f;
    }

    for (int kt = 0; kt < S / TK; kt++) {
        const int k0g = kt * TK;
        __syncthreads();   // previous iteration's smem reads complete

        // Load K (transposed) and V tiles
        for (int idx = tid; idx < TK * D; idx += 256) {
            const int r = idx >> 6;
            const int d = idx & 63;
            KsT[d * PAD + r] = kptr[(size_t)(k0g + r) * (3 * NX) + d];
            Vs[r * PAD + d]  = vptr[(size_t)(k0g + r) * (3 * NX) + d];
        }
        if (tid < TK) mk[tid] = mask[(size_t)b * S + k0g + tid];
        __syncthreads();

        // Scores: s[i][j] = sum_d Q[q][d]*K[k][d]
        float s[4][4];
#pragma unroll
        for (int i = 0; i < 4; i++)
#pragma unroll
            for (int j = 0; j < 4; j++) s[i][j] = 0.f;

#pragma unroll 8
        for (int d = 0; d < D; d++) {
            float4 qa = *(const float4*)&QsT[d * PAD + ty * 4];
            float4 kb = *(const float4*)&KsT[d * PAD + tx * 4];
            const float qv[4] = {qa.x, qa.y, qa.z, qa.w};
            const float kv[4] = {kb.x, kb.y, kb.z, kb.w};
#pragma unroll
            for (int i = 0; i < 4; i++)
#pragma unroll
                for (int j = 0; j < 4; j++)
                    s[i][j] = fmaf(qv[i], kv[j], s[i][j]);
        }

        // scale + mask
        float mkv[4];
#pragma unroll
        for (int j = 0; j < 4; j++) mkv[j] = mk[tx * 4 + j];
#pragma unroll
        for (int i = 0; i < 4; i++)
#pragma unroll
            for (int j = 0; j < 4; j++)
                s[i][j] = fmaf(s[i][j], 0.125f, mkv[j]);

        // Row max over the 16 tx-lanes sharing each q row
        float mt[4];
#pragma unroll
        for (int i = 0; i < 4; i++) {
            mt[i] = fmaxf(fmaxf(s[i][0], s[i][1]), fmaxf(s[i][2], s[i][3]));
        }
#pragma unroll
        for (int off = 1; off < 16; off <<= 1) {
#pragma unroll
            for (int i = 0; i < 4; i++)
                mt[i] = fmaxf(mt[i], __shfl_xor_sync(0xffffffffu, mt[i], off));
        }

        float fac[4], lt[4];
#pragma unroll
        for (int i = 0; i < 4; i++) {
            const float mnew = fmaxf(m_i[i], mt[i]);
            fac[i] = __expf(m_i[i] - mnew);
            m_i[i] = mnew;
            lt[i] = 0.f;
#pragma unroll
            for (int j = 0; j < 4; j++) {
                s[i][j] = __expf(s[i][j] - mnew);
                lt[i] += s[i][j];
            }
        }
#pragma unroll
        for (int off = 1; off < 16; off <<= 1) {
#pragma unroll
            for (int i = 0; i < 4; i++)
                lt[i] += __shfl_xor_sync(0xffffffffu, lt[i], off);
        }
#pragma unroll
        for (int i = 0; i < 4; i++) {
            l_i[i] = l_i[i] * fac[i] + lt[i];
#pragma unroll
            for (int j = 0; j < 4; j++) o[i][j] *= fac[i];
        }

        // Store probabilities transposed: PsT[k][q]
#pragma unroll
        for (int j = 0; j < 4; j++)
#pragma unroll
            for (int i = 0; i < 4; i++)
                PsT[(tx * 4 + j) * PAD + ty * 4 + i] = s[i][j];
        __syncthreads();

        // O += P @ V : o[i][j] += sum_k PsT[k][q] * Vs[k][d]
#pragma unroll 8
        for (int kc = 0; kc < TK; kc++) {
            float4 pa = *(const float4*)&PsT[kc * PAD + ty * 4];
            float4 vb = *(const float4*)&Vs[kc * PAD + tx * 4];
            const float pv[4] = {pa.x, pa.y, pa.z, pa.w};
            const float vv[4] = {vb.x, vb.y, vb.z, vb.w};
#pragma unroll
            for (int i = 0; i < 4; i++)
#pragma unroll
                for (int j = 0; j < 4; j++)
                    o[i][j] = fmaf(pv[i], vv[j], o[i][j]);
        }
    }

    // Normalize and write context, merged-heads layout (B,S,NX)
#pragma unroll
    for (int i = 0; i < 4; i++) {
        const float inv = 1.f / l_i[i];
        const size_t row = (size_t)b * S + q0 + ty * 4 + i;
        float4 ov;
        ov.x = o[i][0] * inv;
        ov.y = o[i][1] * inv;
        ov.z = o[i][2] * inv;
        ov.w = o[i][3] * inv;
        *(float4*)(ctx + row * NX + h * D + tx * 4) = ov;
    }
}

// ----------------------------------------------------------------------------
// Launch
// ----------------------------------------------------------------------------
extern "C" void kernel_launch(void* const* d_in, const int* in_sizes, int n_in,
                              void* d_out, int out_size)
{
    const float* x        = (const float*)d_in[0];  // (4,2048,1024)
    const float* mask     = (const float*)d_in[1];  // (4,1,1,2048)
    const float* c_attn_w = (const float*)d_in[2];  // (1024,3072)
    const float* c_attn_b = (const float*)d_in[3];  // (3072)
    const float* c_proj_w = (const float*)d_in[4];  // (1024,1024)
    const float* c_proj_b = (const float*)d_in[5];  // (1024)
    float* out = (float*)d_out;                     // (4,2048,1024)

    float* qkv = nullptr;
    float* ctx = nullptr;
    cudaGetSymbolAddress((void**)&qkv, g_qkv);
    cudaGetSymbolAddress((void**)&ctx, g_ctx);

    // 1) QKV projection: (8192,1024) @ (1024,3072) + b
    {
        dim3 grid(3 * NX / BN, M_TOT / BM);
        sgemm_bias<<<grid, 256>>>(x, c_attn_w, c_attn_b, qkv, M_TOT, 3 * NX, NX);
    }

    // 2) Flash attention -> ctx (merged heads)
    {
        const int smem = (4 * 64 * PAD + 64) * (int)sizeof(float); // ~69.9 KB
        cudaFuncSetAttribute(flash_attn, cudaFuncAttributeMaxDynamicSharedMemorySize, smem);
        dim3 grid(S / TQ, B * H);
        flash_attn<<<grid, 256, smem>>>(qkv, mask, ctx);
    }

    // 3) Output projection: (8192,1024) @ (1024,1024) + b
    {
        dim3 grid(NX / BN, M_TOT / BM);
        sgemm_bias<<<grid, 256>>>(ctx, c_proj_w, c_proj_b, out, M_TOT, NX, NX);
    }
}

// round 3
// speedup vs baseline: 2.2845x; 2.2845x over previous
#include <cuda_runtime.h>
#include <cuda_bf16.h>
#include <math_constants.h>
#include <cstdint>

// Problem constants
#define B   4
#define S   2048
#define NX  1024
#define H   16
#define D   64
#define M_TOT (B * S)   // 8192

// Scratch
__device__ float g_qkv[(size_t)M_TOT * 3 * NX];   // (8192, 3072)
__device__ float g_ctx[(size_t)M_TOT * NX];       // (8192, 1024)
__device__ float g_wt1[(size_t)3 * NX * NX];      // c_attn_w^T, tf32
__device__ float g_wt2[(size_t)NX * NX];          // c_proj_w^T, tf32

// ---------------------------------------------------------------------------
// Helpers
// ---------------------------------------------------------------------------
__device__ __forceinline__ uint32_t f2tf32(float x) {
    uint32_t u;
    asm("cvt.rna.tf32.f32 %0, %1;" : "=r"(u) : "f"(x));
    return u;
}

// mma.sync m16n8k8 tf32: D = A*B + D (fp32 accum)
__device__ __forceinline__ void mma8(float* c, const uint32_t* a, const uint32_t* b) {
    asm volatile(
        "mma.sync.aligned.m16n8k8.row.col.f32.tf32.tf32.f32 "
        "{%0,%1,%2,%3}, {%4,%5,%6,%7}, {%8,%9}, {%0,%1,%2,%3};"
        : "+f"(c[0]), "+f"(c[1]), "+f"(c[2]), "+f"(c[3])
        : "r"(a[0]), "r"(a[1]), "r"(a[2]), "r"(a[3]), "r"(b[0]), "r"(b[1]));
}

// ---------------------------------------------------------------------------
// Weight transpose + tf32 convert: Wt[n][k] = tf32(W[k][n])
// ---------------------------------------------------------------------------
__global__ void transpose_cvt(const float* __restrict__ W, float* __restrict__ Wt,
                              int K, int N)
{
    __shared__ float t[32][33];
    const int k0 = blockIdx.y * 32, n0 = blockIdx.x * 32;
    const int x = threadIdx.x, y = threadIdx.y;   // 32 x 8
#pragma unroll
    for (int i = 0; i < 32; i += 8)
        t[y + i][x] = W[(size_t)(k0 + y + i) * N + n0 + x];
    __syncthreads();
#pragma unroll
    for (int i = 0; i < 32; i += 8)
        Wt[(size_t)(n0 + y + i) * K + k0 + x] = __uint_as_float(f2tf32(t[x][y + i]));
}

// ---------------------------------------------------------------------------
// tf32 mma GEMM: C[M,N] = A[M,K] @ Bt[N,K]^T + bias[N]
// Block 128x128, K-tile 32, 256 threads = 8 warps; warp tile 64x32.
// ---------------------------------------------------------------------------
#define GLD 36   // smem row stride (floats), conflict-free: (4g+tig) mod 32

__global__ __launch_bounds__(256)
void gemm_mma(const float* __restrict__ A, const float* __restrict__ Bt,
              const float* __restrict__ bias, float* __restrict__ C,
              int M, int N, int K)
{
    __shared__ float As[128][GLD];
    __shared__ float Bs[128][GLD];

    const int tid  = threadIdx.x;
    const int wid  = tid >> 5;
    const int lane = tid & 31;
    const int g    = lane >> 2;   // groupID 0..7
    const int tig  = lane & 3;    // thread-in-group 0..3

    const int brow = blockIdx.y * 128;
    const int bcol = blockIdx.x * 128;
    const int wm = (wid >> 2) * 64;   // warp m offset
    const int wn = (wid & 3) * 32;    // warp n offset

    float c[4][4][4];
#pragma unroll
    for (int mi = 0; mi < 4; mi++)
#pragma unroll
        for (int ni = 0; ni < 4; ni++)
#pragma unroll
            for (int j = 0; j < 4; j++) c[mi][ni][j] = 0.f;

    for (int k0 = 0; k0 < K; k0 += 32) {
        __syncthreads();
#pragma unroll
        for (int i = 0; i < 4; i++) {
            const int v = tid + i * 256;       // 0..1023
            const int r  = v >> 3;             // 0..127
            const int ve = v & 7;              // float4 slot
            float4 av = *(const float4*)(A + (size_t)(brow + r) * K + k0 + ve * 4);
            As[r][ve * 4 + 0] = __uint_as_float(f2tf32(av.x));
            As[r][ve * 4 + 1] = __uint_as_float(f2tf32(av.y));
            As[r][ve * 4 + 2] = __uint_as_float(f2tf32(av.z));
            As[r][ve * 4 + 3] = __uint_as_float(f2tf32(av.w));
            float4 bv = *(const float4*)(Bt + (size_t)(bcol + r) * K + k0 + ve * 4);
            *(float4*)&Bs[r][ve * 4] = bv;
        }
        __syncthreads();

#pragma unroll
        for (int ks = 0; ks < 4; ks++) {
            const int kk = ks * 8;
            uint32_t af[4][4], bf[4][2];
#pragma unroll
            for (int mi = 0; mi < 4; mi++) {
                const int r = wm + mi * 16;
                af[mi][0] = __float_as_uint(As[r + g][kk + tig]);
                af[mi][1] = __float_as_uint(As[r + g + 8][kk + tig]);
                af[mi][2] = __float_as_uint(As[r + g][kk + tig + 4]);
                af[mi][3] = __float_as_uint(As[r + g + 8][kk + tig + 4]);
            }
#pragma unroll
            for (int ni = 0; ni < 4; ni++) {
                const int r = wn + ni * 8;
                bf[ni][0] = __float_as_uint(Bs[r + g][kk + tig]);
                bf[ni][1] = __float_as_uint(Bs[r + g][kk + tig + 4]);
            }
#pragma unroll
            for (int mi = 0; mi < 4; mi++)
#pragma unroll
                for (int ni = 0; ni < 4; ni++)
                    mma8(c[mi][ni], af[mi], bf[ni]);
        }
    }

    // Epilogue
#pragma unroll
    for (int mi = 0; mi < 4; mi++) {
        const int row0 = brow + wm + mi * 16 + g;
#pragma unroll
        for (int ni = 0; ni < 4; ni++) {
            const int col = bcol + wn + ni * 8 + 2 * tig;
            float2 bb = *(const float2*)(bias + col);
            float2 v0, v1;
            v0.x = c[mi][ni][0] + bb.x; v0.y = c[mi][ni][1] + bb.y;
            v1.x = c[mi][ni][2] + bb.x; v1.y = c[mi][ni][3] + bb.y;
            *(float2*)(C + (size_t)row0 * N + col) = v0;
            *(float2*)(C + (size_t)(row0 + 8) * N + col) = v1;
        }
    }
}

// ---------------------------------------------------------------------------
// Flash attention with tf32 mma.
// Block: 4 warps (128 thr). TQ=64 (16 q rows per warp), TK=64, D=64.
// Q frags hoisted to registers. Softmax rows fully within one warp.
// ---------------------------------------------------------------------------
#define AP 68   // smem row stride (floats)

__global__ __launch_bounds__(128)
void flash_attn_mma(const float* __restrict__ qkv, const float* __restrict__ mask,
                    float* __restrict__ ctx)
{
    extern __shared__ float sm[];
    float* Qs  = sm;                 // [64][AP]  (q, d)  tf32
    float* Ks  = Qs + 64 * AP;       // [64][AP]  (k, d)  tf32
    float* VsT = Ks + 64 * AP;       // [64][AP]  (d, k)  tf32
    float* Ps  = VsT + 64 * AP;      // [64][AP]  (q, k)  tf32
    float* mk  = Ps + 64 * AP;       // [64]

    const int bh = blockIdx.y;
    const int b  = bh >> 4;
    const int h  = bh & 15;
    const int q0 = blockIdx.x * 64;

    const int tid  = threadIdx.x;
    const int wid  = tid >> 5;
    const int lane = tid & 31;
    const int g    = lane >> 2;
    const int tig  = lane & 3;
    const int m0   = wid * 16;       // warp's q-row offset in tile

    const size_t base = (size_t)b * S * (3 * NX);
    const float* qptr = qkv + base + (size_t)h * D;
    const float* kptr = qkv + base + NX + (size_t)h * D;
    const float* vptr = qkv + base + 2 * NX + (size_t)h * D;

    // Load Q tile (tf32)
    for (int idx = tid; idx < 64 * 64; idx += 128) {
        const int r = idx >> 6;
        const int d = idx & 63;
        Qs[r * AP + d] = __uint_as_float(f2tf32(qptr[(size_t)(q0 + r) * (3 * NX) + d]));
    }
    __syncthreads();

    // Hoist Q fragments: 8 k-steps x 4 regs
    uint32_t aq[8][4];
#pragma unroll
    for (int ks = 0; ks < 8; ks++) {
        const int kk = ks * 8;
        aq[ks][0] = __float_as_uint(Qs[(m0 + g) * AP + kk + tig]);
        aq[ks][1] = __float_as_uint(Qs[(m0 + g + 8) * AP + kk + tig]);
        aq[ks][2] = __float_as_uint(Qs[(m0 + g) * AP + kk + tig + 4]);
        aq[ks][3] = __float_as_uint(Qs[(m0 + g + 8) * AP + kk + tig + 4]);
    }

    // Per-thread row stats: rows m0+g and m0+g+8
    float mi0 = -CUDART_INF_F, mi1 = -CUDART_INF_F;
    float li0 = 0.f, li1 = 0.f;
    float o[8][4];
#pragma unroll
    for (int ni = 0; ni < 8; ni++)
#pragma unroll
        for (int j = 0; j < 4; j++) o[ni][j] = 0.f;

    for (int kt = 0; kt < S / 64; kt++) {
        const int k0g = kt * 64;
        __syncthreads();   // protect Ks/VsT from previous iteration

        for (int idx = tid; idx < 64 * 64; idx += 128) {
            const int r = idx >> 6;
            const int d = idx & 63;
            Ks[r * AP + d]  = __uint_as_float(f2tf32(kptr[(size_t)(k0g + r) * (3 * NX) + d]));
            VsT[d * AP + r] = __uint_as_float(f2tf32(vptr[(size_t)(k0g + r) * (3 * NX) + d]));
        }
        if (tid < 64) mk[tid] = mask[(size_t)b * S + k0g + tid];
        __syncthreads();

        // ---- QK^T: scores c[8 n-tiles][4]
        float c[8][4];
#pragma unroll
        for (int ni = 0; ni < 8; ni++)
#pragma unroll
            for (int j = 0; j < 4; j++) c[ni][j] = 0.f;

#pragma unroll
        for (int ks = 0; ks < 8; ks++) {
            const int kk = ks * 8;
            uint32_t bf[8][2];
#pragma unroll
            for (int ni = 0; ni < 8; ni++) {
                bf[ni][0] = __float_as_uint(Ks[(ni * 8 + g) * AP + kk + tig]);
                bf[ni][1] = __float_as_uint(Ks[(ni * 8 + g) * AP + kk + tig + 4]);
            }
#pragma unroll
            for (int ni = 0; ni < 8; ni++)
                mma8(c[ni], aq[ks], bf[ni]);
        }

        // ---- scale + mask
#pragma unroll
        for (int ni = 0; ni < 8; ni++) {
            const int jc = ni * 8 + 2 * tig;
            const float mk0 = mk[jc], mk1 = mk[jc + 1];
            c[ni][0] = fmaf(c[ni][0], 0.125f, mk0);
            c[ni][1] = fmaf(c[ni][1], 0.125f, mk1);
            c[ni][2] = fmaf(c[ni][2], 0.125f, mk0);
            c[ni][3] = fmaf(c[ni][3], 0.125f, mk1);
        }

        // ---- row max (rows g / g+8), reduce over tig via shfl
        float mt0 = -CUDART_INF_F, mt1 = -CUDART_INF_F;
#pragma unroll
        for (int ni = 0; ni < 8; ni++) {
            mt0 = fmaxf(mt0, fmaxf(c[ni][0], c[ni][1]));
            mt1 = fmaxf(mt1, fmaxf(c[ni][2], c[ni][3]));
        }
        mt0 = fmaxf(mt0, __shfl_xor_sync(0xffffffffu, mt0, 1));
        mt0 = fmaxf(mt0, __shfl_xor_sync(0xffffffffu, mt0, 2));
        mt1 = fmaxf(mt1, __shfl_xor_sync(0xffffffffu, mt1, 1));
        mt1 = fmaxf(mt1, __shfl_xor_sync(0xffffffffu, mt1, 2));

        const float mn0 = fmaxf(mi0, mt0);
        const float mn1 = fmaxf(mi1, mt1);
        const float fac0 = __expf(mi0 - mn0);
        const float fac1 = __expf(mi1 - mn1);
        mi0 = mn0; mi1 = mn1;

        float lt0 = 0.f, lt1 = 0.f;
#pragma unroll
        for (int ni = 0; ni < 8; ni++) {
            c[ni][0] = __expf(c[ni][0] - mn0);
            c[ni][1] = __expf(c[ni][1] - mn0);
            c[ni][2] = __expf(c[ni][2] - mn1);
            c[ni][3] = __expf(c[ni][3] - mn1);
            lt0 += c[ni][0] + c[ni][1];
            lt1 += c[ni][2] + c[ni][3];
        }
        lt0 += __shfl_xor_sync(0xffffffffu, lt0, 1);
        lt0 += __shfl_xor_sync(0xffffffffu, lt0, 2);
        lt1 += __shfl_xor_sync(0xffffffffu, lt1, 1);
        lt1 += __shfl_xor_sync(0xffffffffu, lt1, 2);
        li0 = li0 * fac0 + lt0;
        li1 = li1 * fac1 + lt1;

        // rescale output accumulators
#pragma unroll
        for (int ni = 0; ni < 8; ni++) {
            o[ni][0] *= fac0; o[ni][1] *= fac0;
            o[ni][2] *= fac1; o[ni][3] *= fac1;
        }

        // ---- store P (tf32) to smem, own rows only
#pragma unroll
        for (int ni = 0; ni < 8; ni++) {
            const int jc = ni * 8 + 2 * tig;
            float2 p0, p1;
            p0.x = __uint_as_float(f2tf32(c[ni][0]));
            p0.y = __uint_as_float(f2tf32(c[ni][1]));
            p1.x = __uint_as_float(f2tf32(c[ni][2]));
            p1.y = __uint_as_float(f2tf32(c[ni][3]));
            *(float2*)&Ps[(m0 + g) * AP + jc]     = p0;
            *(float2*)&Ps[(m0 + g + 8) * AP + jc] = p1;
        }
        __syncwarp();

        // ---- O += P @ V
#pragma unroll
        for (int ks = 0; ks < 8; ks++) {
            const int kk = ks * 8;
            uint32_t ap[4];
            ap[0] = __float_as_uint(Ps[(m0 + g) * AP + kk + tig]);
            ap[1] = __float_as_uint(Ps[(m0 + g + 8) * AP + kk + tig]);
            ap[2] = __float_as_uint(Ps[(m0 + g) * AP + kk + tig + 4]);
            ap[3] = __float_as_uint(Ps[(m0 + g + 8) * AP + kk + tig + 4]);
            uint32_t bf[8][2];
#pragma unroll
            for (int ni = 0; ni < 8; ni++) {
                bf[ni][0] = __float_as_uint(VsT[(ni * 8 + g) * AP + kk + tig]);
                bf[ni][1] = __float_as_uint(VsT[(ni * 8 + g) * AP + kk + tig + 4]);
            }
#pragma unroll
            for (int ni = 0; ni < 8; ni++)
                mma8(o[ni], ap, bf[ni]);
        }
    }

    // ---- normalize + write merged-heads context
    const float inv0 = 1.f / li0;
    const float inv1 = 1.f / li1;
    const size_t row0 = (size_t)b * S + q0 + m0 + g;
#pragma unroll
    for (int ni = 0; ni < 8; ni++) {
        const int col = h * D + ni * 8 + 2 * tig;
        float2 v0, v1;
        v0.x = o[ni][0] * inv0; v0.y = o[ni][1] * inv0;
        v1.x = o[ni][2] * inv1; v1.y = o[ni][3] * inv1;
        *(float2*)(ctx + row0 * NX + col)       = v0;
        *(float2*)(ctx + (row0 + 8) * NX + col) = v1;
    }
}

// ---------------------------------------------------------------------------
// Launch
// ---------------------------------------------------------------------------
extern "C" void kernel_launch(void* const* d_in, const int* in_sizes, int n_in,
                              void* d_out, int out_size)
{
    const float* x        = (const float*)d_in[0];
    const float* mask     = (const float*)d_in[1];
    const float* c_attn_w = (const float*)d_in[2];
    const float* c_attn_b = (const float*)d_in[3];
    const float* c_proj_w = (const float*)d_in[4];
    const float* c_proj_b = (const float*)d_in[5];
    float* out = (float*)d_out;

    float *qkv, *ctx, *wt1, *wt2;
    cudaGetSymbolAddress((void**)&qkv, g_qkv);
    cudaGetSymbolAddress((void**)&ctx, g_ctx);
    cudaGetSymbolAddress((void**)&wt1, g_wt1);
    cudaGetSymbolAddress((void**)&wt2, g_wt2);

    // 0) Transpose + tf32-convert weights
    transpose_cvt<<<dim3(3 * NX / 32, NX / 32), dim3(32, 8)>>>(c_attn_w, wt1, NX, 3 * NX);
    transpose_cvt<<<dim3(NX / 32, NX / 32),     dim3(32, 8)>>>(c_proj_w, wt2, NX, NX);

    // 1) QKV projection
    gemm_mma<<<dim3(3 * NX / 128, M_TOT / 128), 256>>>(x, wt1, c_attn_b, qkv,
                                                       M_TOT, 3 * NX, NX);

    // 2) Flash attention
    {
        const int smem = (4 * 64 * AP + 64) * (int)sizeof(float);  // ~70 KB
        cudaFuncSetAttribute(flash_attn_mma, cudaFuncAttributeMaxDynamicSharedMemorySize, smem);
        dim3 grid(S / 64, B * H);
        flash_attn_mma<<<grid, 128, smem>>>(qkv, mask, ctx);
    }

    // 3) Output projection
    gemm_mma<<<dim3(NX / 128, M_TOT / 128), 256>>>(ctx, wt2, c_proj_b, out,
                                                   M_TOT, NX, NX);
}